// round 1
// baseline (speedup 1.0000x reference)
#include <cuda_runtime.h>
#include <math.h>

// ---------------- fixed geometry ----------------
#define IMG   512
#define NDET  768
#define NVIEWS 360
#define BATCH 2

static __device__ __constant__ const double DG_D = 1.2858 / (595.0 + 490.6); // DGAMMA (f64)
#define DGF   ((float)(1.2858 / (595.0 + 490.6)))
#define INVDG (1.0f / DGF)
#define DSOF  595.0f
#define PIXF  0.7433f
#define SCALEF ((float)(2.0 * M_PI / 360.0))

// ---------------- device scratch (no allocations allowed) ----------------
__device__ float  d_g[2 * NDET - 1];        // ramp kernel, index i <-> n = i-767
__device__ float  d_cosw[NDET];             // DSO * cos(gamma_j)
__device__ float  d_cb[NVIEWS], d_sb[NVIEWS];
__device__ float4 d_qi[NVIEWS * NDET];      // (q0[k], q0[k+1], q1[k], q1[k+1])

// ---------------- 1) table prep ----------------
__global__ void prep_kernel() {
    int i = blockIdx.x * blockDim.x + threadIdx.x;
    if (i < 2 * NDET - 1) {
        int n = i - (NDET - 1);
        double v = 0.0;
        if (n == 0) {
            v = 1.0 / (8.0 * DG_D * DG_D);
        } else if (n & 1) {
            double s = M_PI * sin((double)n * DG_D);
            v = -0.5 / (s * s);
        }
        d_g[i] = (float)v;
    } else if (i < 2 * NDET - 1 + NDET) {
        int j = i - (2 * NDET - 1);
        float gam = ((float)j - 383.5f) * DGF;
        d_cosw[j] = 595.0f * cosf(gam);
    } else if (i < 2 * NDET - 1 + NDET + NVIEWS) {
        int v = i - (2 * NDET - 1 + NDET);
        double b = 2.0 * M_PI * (double)v / 360.0;
        d_cb[v] = (float)cos(b);
        d_sb[v] = (float)sin(b);
    }
}

// ---------------- 2) ramp filter (direct sparse convolution) ----------------
// q[k] = DG * ( p1[k]*g(0) + sum_{j : (k-j) odd} p1[j]*g(k-j) )
// One block per view; 256 threads; each thread owns k, k+256, k+512 (same parity).
__global__ void __launch_bounds__(256) filter_kernel(const float* __restrict__ proj) {
    __shared__ float p1s[2][NDET];
    __shared__ float gs[2 * NDET];      // 1535 used
    __shared__ float qs[2][NDET];

    const int v = blockIdx.x;
    const int t = threadIdx.x;

    for (int j = t; j < NDET; j += 256) {
        float cw = d_cosw[j];
        p1s[0][j] = proj[(0 * NVIEWS + v) * NDET + j] * cw;
        p1s[1][j] = proj[(1 * NVIEWS + v) * NDET + j] * cw;
    }
    for (int i = t; i < 2 * NDET - 1; i += 256) gs[i] = d_g[i];
    __syncthreads();

    const float g0 = gs[NDET - 1];
    const int k0 = t;            // k0, k0+256, k0+512 all share parity
    float a00 = p1s[0][k0]        * g0;
    float a01 = p1s[0][k0 + 256]  * g0;
    float a02 = p1s[0][k0 + 512]  * g0;
    float a10 = p1s[1][k0]        * g0;
    float a11 = p1s[1][k0 + 256]  * g0;
    float a12 = p1s[1][k0 + 512]  * g0;

    const int j0 = (k0 & 1) ^ 1;  // opposite parity of k -> odd offsets only
    const float* gb = &gs[k0 - j0 + (NDET - 1)];   // gb[-(j-j0)] pattern
    #pragma unroll 4
    for (int j = j0; j < NDET; j += 2) {
        float pA = p1s[0][j];
        float pB = p1s[1][j];
        int gi = k0 - j + (NDET - 1);
        float gA = gs[gi];
        float gBv = gs[gi + 256];
        float gC = gs[gi + 512];
        a00 = fmaf(pA, gA,  a00);
        a01 = fmaf(pA, gBv, a01);
        a02 = fmaf(pA, gC,  a02);
        a10 = fmaf(pB, gA,  a10);
        a11 = fmaf(pB, gBv, a11);
        a12 = fmaf(pB, gC,  a12);
    }
    (void)gb;

    qs[0][k0]       = a00 * DGF;
    qs[0][k0 + 256] = a01 * DGF;
    qs[0][k0 + 512] = a02 * DGF;
    qs[1][k0]       = a10 * DGF;
    qs[1][k0 + 256] = a11 * DGF;
    qs[1][k0 + 512] = a12 * DGF;
    __syncthreads();

    for (int k = t; k < NDET; k += 256) {
        int k1 = min(k + 1, NDET - 1);
        d_qi[v * NDET + k] = make_float4(qs[0][k], qs[0][k1], qs[1][k], qs[1][k1]);
    }
}

// ---------------- 3) pixel-driven backprojection ----------------
__global__ void __launch_bounds__(256) backproj_kernel(float* __restrict__ out) {
    __shared__ float scb[NVIEWS], ssb[NVIEWS];
    const int t = threadIdx.y * 32 + threadIdx.x;
    for (int i = t; i < NVIEWS; i += 256) { scb[i] = d_cb[i]; ssb[i] = d_sb[i]; }
    __syncthreads();

    const int x = blockIdx.x * 32 + threadIdx.x;
    const int y = blockIdx.y * 8  + threadIdx.y;
    const float X = ((float)x - 255.5f) * PIXF;
    const float Y = ((float)y - 255.5f) * PIXF;

    float acc0 = 0.0f, acc1 = 0.0f;

    #pragma unroll 2
    for (int v = 0; v < NVIEWS; v++) {
        float cb = scb[v], sb = ssb[v];
        float vx = X - DSOF * cb;
        float vy = Y - DSOF * sb;
        float dotv  = -(cb * vx + sb * vy);     // always > 0 inside image
        float cross = -(cb * vy - sb * vx);
        float gidx = atanf(__fdividef(cross, dotv)) * INVDG + 383.5f;
        if (gidx >= 0.0f && gidx <= (float)(NDET - 1)) {
            int i0 = min((int)gidx, NDET - 2);       // gidx >= 0 -> trunc == floor
            float w = fminf(gidx - (float)i0, 1.0f);
            float4 qv = d_qi[v * NDET + i0];
            float L2 = vx * vx + vy * vy;
            float rin = __fdividef(1.0f, L2);
            float v0 = qv.x * (1.0f - w) + qv.y * w;
            float v1 = qv.z * (1.0f - w) + qv.w * w;
            acc0 = fmaf(v0, rin, acc0);
            acc1 = fmaf(v1, rin, acc1);
        }
    }

    out[(size_t)y * IMG + x]                 = acc0 * SCALEF;
    out[(size_t)IMG * IMG + y * IMG + x]     = acc1 * SCALEF;
}

// ---------------- launch ----------------
extern "C" void kernel_launch(void* const* d_in, const int* in_sizes, int n_in,
                              void* d_out, int out_size) {
    (void)in_sizes; (void)n_in; (void)out_size;
    const float* proj = (const float*)d_in[0];
    float* out = (float*)d_out;

    prep_kernel<<<(2 * NDET - 1 + NDET + NVIEWS + 255) / 256, 256>>>();
    filter_kernel<<<NVIEWS, 256>>>(proj);
    dim3 blk(32, 8);
    dim3 grd(IMG / 32, IMG / 8);
    backproj_kernel<<<grd, blk>>>(out);
}